// round 11
// baseline (speedup 1.0000x reference)
#include <cuda_runtime.h>
#include <cuda_bf16.h>
#include <cstdint>
#include <math.h>

// MMDDistance on GB300 (sm_103 base target): split-bf16 3-pass HMMA gram,
// prepacked bf16(hi,lo), 4-stage cp.async pipeline (CHUNK=16), fused epilogue.
//
//  k_prep : fp32 -> (hi,lo) bf16 prepack + row sq norms + column sums;
//           last-arriving block computes bandwidth (g_negc)
//  k_main : one 128x128 upper-triangle tile per CTA; 16 K-chunks of 16,
//           4-stage cp.async ring overlapping MMA; one syncthreads/chunk;
//           epilogue: L2 -> one EX2 + 4 squarings -> signed partial;
//           last-arriving CTA does the deterministic final reduction.

#define NROWS 8192
#define NX    4096
#define DDIM  256
#define TB    128
#define NTILE 64
#define NWORK (NTILE * (NTILE + 1) / 2)   // 2080 upper-triangle tiles
#define CHUNK 16
#define NCHUNK (DDIM / CHUNK)              // 16
#define NSTAGE 4
#define ROWB  32                           // smem row bytes (16 bf16)
#define TILEC (TB * ROWB)                  // 4096 B per tile per stage
#define STAGEB (4 * TILEC)                 // 16384 B per stage
#define PBLK  512                          // k_prep blocks (16 rows each)

__device__ __nv_bfloat16 g_hi[NROWS * DDIM];
__device__ __nv_bfloat16 g_lo[NROWS * DDIM];
__device__ float  g_sq[NROWS];
__device__ double g_p_sqsum[PBLK];
__device__ float  g_p_colf[PBLK][DDIM];
__device__ float  g_negc;                  // -log2(e)/(16*bandwidth)
__device__ double g_partial[NWORK];
__device__ unsigned int g_done_prep;       // zero-init; self-resetting
__device__ unsigned int g_done_main;       // zero-init; self-resetting

// ---------------------------------------------------------------- helpers
__device__ __forceinline__ uint32_t smem_addr_u32(const void* p) {
    uint32_t a;
    asm("{ .reg .u64 t; cvta.to.shared.u64 t, %1; cvt.u32.u64 %0, t; }"
        : "=r"(a) : "l"(p));
    return a;
}
__device__ __forceinline__ void ldsm4(uint32_t addr, uint32_t r[4]) {
    asm volatile("ldmatrix.sync.aligned.m8n8.x4.shared.b16 {%0,%1,%2,%3}, [%4];"
                 : "=r"(r[0]), "=r"(r[1]), "=r"(r[2]), "=r"(r[3]) : "r"(addr));
}
__device__ __forceinline__ void mma16816(float d[4], const uint32_t a[4],
                                         uint32_t b0, uint32_t b1) {
    asm volatile(
        "mma.sync.aligned.m16n8k16.row.col.f32.bf16.bf16.f32 "
        "{%0,%1,%2,%3}, {%4,%5,%6,%7}, {%8,%9}, {%0,%1,%2,%3};"
        : "+f"(d[0]), "+f"(d[1]), "+f"(d[2]), "+f"(d[3])
        : "r"(a[0]), "r"(a[1]), "r"(a[2]), "r"(a[3]), "r"(b0), "r"(b1));
}
__device__ __forceinline__ void cpasync16(uint32_t dst, const void* src) {
    asm volatile("cp.async.ca.shared.global [%0], [%1], 16;"
                 :: "r"(dst), "l"(src) : "memory");
}
// 32B-row swizzle: 16B unit u (0/1) at row r -> u ^ ((r>>2)&1).
// Conflict-free for ldmatrix 8-lane phases (granule (2r+s)&7 covers 0..7)
// and for cp.async write phases.
__device__ __forceinline__ uint32_t swz_off(int r, int u) {
    return (uint32_t)(r * ROWB + ((u ^ ((r >> 2) & 1)) << 4));
}

// ---------------------------------------------------------------------------
// k_prep: PBLK blocks x 256 thr; block b covers rows [16b, 16b+16).
__global__ __launch_bounds__(256) void k_prep(const float* __restrict__ x,
                                              const float* __restrict__ y) {
    const int b = blockIdx.x, r0 = b * 16;
    const int w = threadIdx.x >> 5, lane = threadIdx.x & 31;
    __shared__ double ws[8];
    __shared__ double red[256];
    __shared__ int last_sh;

    const float* base = (r0 < NX) ? (x + (size_t)r0 * DDIM)
                                  : (y + (size_t)(r0 - NX) * DDIM);

    // conversion + column partials: thread owns column k over 16 rows
    {
        const int k = threadIdx.x;
        float acc = 0.f;
#pragma unroll
        for (int i = 0; i < 16; i++) {
            float v = base[(size_t)i * DDIM + k];
            __nv_bfloat16 h = __float2bfloat16_rn(v);
            float l = v - __bfloat162float(h);
            size_t idx = (size_t)(r0 + i) * DDIM + k;
            g_hi[idx] = h;
            g_lo[idx] = __float2bfloat16_rn(l);
            acc += v;
        }
        g_p_colf[b][k] = acc;
    }

    // row squared norms: warp handles 2 rows (cache-hot)
    double wsum = 0.0;
#pragma unroll
    for (int rr = 0; rr < 2; rr++) {
        int r = w * 2 + rr;
        const float* p = base + (size_t)r * DDIM;
        float s = 0.f;
#pragma unroll
        for (int k = lane; k < DDIM; k += 32) { float v = p[k]; s = fmaf(v, v, s); }
#pragma unroll
        for (int off = 16; off; off >>= 1) s += __shfl_down_sync(0xffffffffu, s, off);
        if (lane == 0) { g_sq[r0 + r] = s; wsum += (double)s; }
    }
    if (lane == 0) ws[w] = wsum;
    __syncthreads();
    if (threadIdx.x == 0) {
        double t = 0.0;
#pragma unroll
        for (int i = 0; i < 8; i++) t += ws[i];
        g_p_sqsum[b] = t;
        __threadfence();
        last_sh = (atomicAdd(&g_done_prep, 1u) == PBLK - 1);
    }
    __syncthreads();

    if (!last_sh) return;
    // ---- last-arriving block: bandwidth ----
    __threadfence();
    const int t = threadIdx.x;
    float cs = 0.f;
#pragma unroll 8
    for (int bb = 0; bb < PBLK; bb++) cs += g_p_colf[bb][t];
    red[t] = (double)cs * (double)cs;
    __syncthreads();
    for (int off = 128; off; off >>= 1) {
        if (t < off) red[t] += red[t + off];
        __syncthreads();
    }
    double colsq = red[0];
    __syncthreads();
    double q = 0.0;
    for (int i = t; i < PBLK; i += 256) q += g_p_sqsum[i];
    red[t] = q;
    __syncthreads();
    for (int off = 128; off; off >>= 1) {
        if (t < off) red[t] += red[t + off];
        __syncthreads();
    }
    if (t == 0) {
        double n = (double)NROWS;
        double sumL2 = 2.0 * n * red[0] - 2.0 * colsq;
        double bw = sumL2 / (n * n - n) / 4.0;   // / KERNEL_MUL^(KERNEL_NUM//2)
        g_negc = (float)(-M_LOG2E / (16.0 * bw));
        g_done_prep = 0;                          // reset for next replay
    }
}

// ---------------------------------------------------------------------------
// k_main: 2080 CTAs, one upper-triangle 128x128 tile each; 4-stage pipeline.
__global__ __launch_bounds__(256, 2) void k_main(float* __restrict__ out) {
    const int u = blockIdx.x;
    int bi = (int)((2.0f * NTILE + 1.0f
                    - sqrtf((2.0f * NTILE + 1.0f) * (2.0f * NTILE + 1.0f)
                            - 8.0f * (float)u)) * 0.5f);
    while (bi > 0 && bi * NTILE - bi * (bi - 1) / 2 > u) bi--;
    while ((bi + 1) * NTILE - (bi + 1) * bi / 2 <= u) bi++;
    const int bj = bi + (u - (bi * NTILE - bi * (bi - 1) / 2));

    extern __shared__ __align__(16) char dsm[];
    __shared__ float  sqA[TB], sqB[TB];
    __shared__ double red[256];
    __shared__ int last_sh;

    const int t    = threadIdx.x;
    const int lane = t & 31;
    const int w    = t >> 5;
    const int wr   = w & 3;          // warp row block  (32 rows)
    const int wc   = w >> 2;         // warp col block  (64 cols)

    const uint32_t sbase = smem_addr_u32(dsm);

    if (t < TB)      sqA[t]      = g_sq[bi * TB + t];
    else             sqB[t - TB] = g_sq[bj * TB + (t - TB)];

    const size_t rowA = (size_t)bi * TB * DDIM;
    const size_t rowB = (size_t)bj * TB * DDIM;
    // staging lane constants: row = t>>1, 16B unit = t&1
    const int crow = t >> 1, cun = t & 1;
    const uint32_t dst_off = swz_off(crow, cun);
    const size_t   src_off = (size_t)crow * DDIM + cun * 8;
    const __nv_bfloat16* srcT[4] = {g_hi + rowA + src_off, g_lo + rowA + src_off,
                                    g_hi + rowB + src_off, g_lo + rowB + src_off};

    // ldsm per-lane constant offsets (stage-relative)
    const int laneR = lane & 15, laneU = lane >> 4;
    uint32_t aoff[2][2], boff[2][2][2];
#pragma unroll
    for (int m = 0; m < 2; m++) {
        int r = wr * 32 + m * 16 + laneR;
        aoff[m][0] = 0 * TILEC + swz_off(r, laneU);   // Ahi
        aoff[m][1] = 1 * TILEC + swz_off(r, laneU);   // Alo
    }
#pragma unroll
    for (int h = 0; h < 2; h++)
#pragma unroll
        for (int s = 0; s < 2; s++) {
            int r = wc * 64 + h * 32 + s * 16 + laneR;
            boff[h][s][0] = 2 * TILEC + swz_off(r, laneU);   // Bhi
            boff[h][s][1] = 3 * TILEC + swz_off(r, laneU);   // Blo
        }

    float acc[2][8][4];
#pragma unroll
    for (int m = 0; m < 2; m++)
#pragma unroll
        for (int n = 0; n < 8; n++)
#pragma unroll
            for (int q = 0; q < 4; q++) acc[m][n][q] = 0.f;

#define STAGE(cc)                                                             \
    do {                                                                      \
        const uint32_t sb_ = sbase + (uint32_t)(((cc) & 3) * STAGEB);         \
        _Pragma("unroll")                                                     \
        for (int tl = 0; tl < 4; tl++)                                        \
            cpasync16(sb_ + tl * TILEC + dst_off, srcT[tl] + (cc) * CHUNK);   \
        asm volatile("cp.async.commit_group;" ::: "memory");                  \
    } while (0)

    // prologue: stages 0..2 in flight
    STAGE(0); STAGE(1); STAGE(2);

#pragma unroll 4
    for (int c = 0; c < NCHUNK; c++) {
        // chunk c complete (<=2 newer groups pending)
        if (c <= NCHUNK - 3)      asm volatile("cp.async.wait_group 2;" ::: "memory");
        else if (c == NCHUNK - 2) asm volatile("cp.async.wait_group 1;" ::: "memory");
        else                      asm volatile("cp.async.wait_group 0;" ::: "memory");
        __syncthreads();   // chunk c visible to all; slot (c+3)&3's readers done
        if (c + 3 < NCHUNK) STAGE(c + 3);

        const uint32_t sb = sbase + (uint32_t)((c & 3) * STAGEB);
        uint32_t ah[2][4], al[2][4];
#pragma unroll
        for (int m = 0; m < 2; m++) {
            ldsm4(sb + aoff[m][0], ah[m]);
            ldsm4(sb + aoff[m][1], al[m]);
        }
#pragma unroll
        for (int h = 0; h < 2; h++) {
            uint32_t bh[2][4], bl[2][4];
#pragma unroll
            for (int s = 0; s < 2; s++) {
                ldsm4(sb + boff[h][s][0], bh[s]);
                ldsm4(sb + boff[h][s][1], bl[s]);
            }
#pragma unroll
            for (int m = 0; m < 2; m++)    // pass 1: hi*hi
#pragma unroll
                for (int s = 0; s < 2; s++)
#pragma unroll
                    for (int sub = 0; sub < 2; sub++)
                        mma16816(acc[m][h * 4 + s * 2 + sub], ah[m],
                                 bh[s][sub], bh[s][sub + 2]);
#pragma unroll
            for (int m = 0; m < 2; m++)    // pass 2: hi*lo
#pragma unroll
                for (int s = 0; s < 2; s++)
#pragma unroll
                    for (int sub = 0; sub < 2; sub++)
                        mma16816(acc[m][h * 4 + s * 2 + sub], ah[m],
                                 bl[s][sub], bl[s][sub + 2]);
#pragma unroll
            for (int m = 0; m < 2; m++)    // pass 3: lo*hi
#pragma unroll
                for (int s = 0; s < 2; s++)
#pragma unroll
                    for (int sub = 0; sub < 2; sub++)
                        mma16816(acc[m][h * 4 + s * 2 + sub], al[m],
                                 bh[s][sub], bh[s][sub + 2]);
        }
    }
#undef STAGE

    // ---- epilogue: 5-kernel sum per pair ----
    const float negc = g_negc;
    const int g  = lane >> 2;
    const int c2 = (lane & 3) * 2;
    float fsum = 0.f;
#pragma unroll
    for (int m = 0; m < 2; m++) {
        const int r0 = wr * 32 + m * 16 + g;
        const float s0 = sqA[r0], s1 = sqA[r0 + 8];
#pragma unroll
        for (int nb = 0; nb < 8; nb++) {
            const int cc = wc * 64 + nb * 8 + c2;
            const float t0 = sqB[cc], t1 = sqB[cc + 1];
#pragma unroll
            for (int q = 0; q < 4; q++) {
                const float sr = (q >= 2) ? s1 : s0;
                const float sc = (q & 1) ? t1 : t0;
                float L2 = fmaxf(sr + sc - 2.f * acc[m][nb][q], 0.f);
                float v;
                asm("ex2.approx.ftz.f32 %0, %1;" : "=f"(v) : "f"(L2 * negc));
                float v2 = v * v, v4 = v2 * v2, v8 = v4 * v4, v16 = v8 * v8;
                fsum += v + v2 + v4 + v8 + v16;
            }
        }
    }
    double sgnw = ((bi < 32) == (bj < 32)) ? 1.0 : -1.0;
    if (bj != bi) sgnw *= 2.0;
    red[t] = (double)fsum * sgnw;
    __syncthreads();
    for (int off = 128; off; off >>= 1) {
        if (t < off) red[t] += red[t + off];
        __syncthreads();
    }
    if (t == 0) {
        g_partial[u] = red[0];
        __threadfence();
        last_sh = (atomicAdd(&g_done_main, 1u) == NWORK - 1);
    }
    __syncthreads();

    if (!last_sh) return;
    // ---- last-arriving CTA: deterministic final reduction ----
    __threadfence();
    double s = 0.0;
    for (int i = t; i < NWORK; i += 256) s += g_partial[i];
    red[t] = s;
    __syncthreads();
    for (int off = 128; off; off >>= 1) {
        if (t < off) red[t] += red[t + off];
        __syncthreads();
    }
    if (t == 0) {
        out[0] = (float)(red[0] / ((double)NX * (double)NX));
        g_done_main = 0;                          // reset for next replay
    }
}

// ---------------------------------------------------------------------------
#define SMEM_DYN (NSTAGE * STAGEB)   // 65536 B -> 2 CTAs/SM

extern "C" void kernel_launch(void* const* d_in, const int* in_sizes, int n_in,
                              void* d_out, int out_size) {
    const float* x = (const float*)d_in[0];
    const float* y = (const float*)d_in[1];
    (void)in_sizes; (void)n_in; (void)out_size;

    k_prep<<<PBLK, 256>>>(x, y);
    cudaFuncSetAttribute(k_main, cudaFuncAttributeMaxDynamicSharedMemorySize, SMEM_DYN);
    k_main<<<NWORK, 256, SMEM_DYN>>>((float*)d_out);
}

// round 12
// speedup vs baseline: 1.0534x; 1.0534x over previous
#include <cuda_runtime.h>
#include <cuda_bf16.h>
#include <cstdint>
#include <math.h>

// MMDDistance on GB300 (sm_103 base target): split-bf16 3-pass HMMA gram,
// prepacked bf16(hi,lo), 3-stage cp.async ring (CHUNK=32, 1 barrier/chunk).
//
//  k_prep : fp32 -> (hi,lo) bf16 prepack + row sq norms + column sums;
//           last-arriving block computes bandwidth (g_negc)
//  k_main : one 128x128 upper-triangle tile per CTA; 8 K-chunks of 32,
//           3-stage cp.async ring (2 chunks in flight under MMA);
//           interleaved 3-pass MMA (R8 order); EX2 kernel-sum epilogue;
//           last-arriving CTA does the deterministic final reduction.

#define NROWS 8192
#define NX    4096
#define DDIM  256
#define TB    128
#define NTILE 64
#define NWORK (NTILE * (NTILE + 1) / 2)   // 2080 upper-triangle tiles
#define CHUNK 32
#define NCHUNK (DDIM / CHUNK)              // 8
#define NSTAGE 3
#define ROWB  64                           // smem row bytes (32 bf16)
#define TILEC (TB * ROWB)                  // 8192 B per tile per stage
#define STAGEB (4 * TILEC)                 // 32768 B per stage
#define PBLK  512                          // k_prep blocks (16 rows each)

__device__ __nv_bfloat16 g_hi[NROWS * DDIM];
__device__ __nv_bfloat16 g_lo[NROWS * DDIM];
__device__ float  g_sq[NROWS];
__device__ double g_p_sqsum[PBLK];
__device__ float  g_p_colf[PBLK][DDIM];
__device__ float  g_negc;                  // -log2(e)/(16*bandwidth)
__device__ double g_partial[NWORK];
__device__ unsigned int g_done_prep;       // zero-init; self-resetting
__device__ unsigned int g_done_main;       // zero-init; self-resetting

// ---------------------------------------------------------------- helpers
__device__ __forceinline__ uint32_t smem_addr_u32(const void* p) {
    uint32_t a;
    asm("{ .reg .u64 t; cvta.to.shared.u64 t, %1; cvt.u32.u64 %0, t; }"
        : "=r"(a) : "l"(p));
    return a;
}
__device__ __forceinline__ void ldsm4(uint32_t addr, uint32_t r[4]) {
    asm volatile("ldmatrix.sync.aligned.m8n8.x4.shared.b16 {%0,%1,%2,%3}, [%4];"
                 : "=r"(r[0]), "=r"(r[1]), "=r"(r[2]), "=r"(r[3]) : "r"(addr));
}
__device__ __forceinline__ void mma16816(float d[4], const uint32_t a[4],
                                         uint32_t b0, uint32_t b1) {
    asm volatile(
        "mma.sync.aligned.m16n8k16.row.col.f32.bf16.bf16.f32 "
        "{%0,%1,%2,%3}, {%4,%5,%6,%7}, {%8,%9}, {%0,%1,%2,%3};"
        : "+f"(d[0]), "+f"(d[1]), "+f"(d[2]), "+f"(d[3])
        : "r"(a[0]), "r"(a[1]), "r"(a[2]), "r"(a[3]), "r"(b0), "r"(b1));
}
__device__ __forceinline__ void cpasync16(uint32_t dst, const void* src) {
    asm volatile("cp.async.ca.shared.global [%0], [%1], 16;"
                 :: "r"(dst), "l"(src) : "memory");
}
// 64B-row swizzle: 16B unit u (0..3) at row r -> u ^ ((r>>1)&3).
// Conflict-free for ldmatrix 8-lane phases (4 even rows hit granules {0..3}
// permuted, 4 odd rows hit {4..7} permuted) and cp.async write phases
// (4 lanes per row, distinct granules).
__device__ __forceinline__ uint32_t swz_off(int r, int u) {
    return (uint32_t)(r * ROWB + ((u ^ ((r >> 1) & 3)) << 4));
}

// ---------------------------------------------------------------------------
// k_prep: PBLK blocks x 256 thr; block b covers rows [16b, 16b+16).
__global__ __launch_bounds__(256) void k_prep(const float* __restrict__ x,
                                              const float* __restrict__ y) {
    const int b = blockIdx.x, r0 = b * 16;
    const int w = threadIdx.x >> 5, lane = threadIdx.x & 31;
    __shared__ double ws[8];
    __shared__ double red[256];
    __shared__ int last_sh;

    const float* base = (r0 < NX) ? (x + (size_t)r0 * DDIM)
                                  : (y + (size_t)(r0 - NX) * DDIM);

    // conversion + column partials: thread owns column k over 16 rows
    {
        const int k = threadIdx.x;
        float acc = 0.f;
#pragma unroll
        for (int i = 0; i < 16; i++) {
            float v = base[(size_t)i * DDIM + k];
            __nv_bfloat16 h = __float2bfloat16_rn(v);
            float l = v - __bfloat162float(h);
            size_t idx = (size_t)(r0 + i) * DDIM + k;
            g_hi[idx] = h;
            g_lo[idx] = __float2bfloat16_rn(l);
            acc += v;
        }
        g_p_colf[b][k] = acc;
    }

    // row squared norms (cache-hot)
    double wsum = 0.0;
#pragma unroll
    for (int rr = 0; rr < 2; rr++) {
        int r = w * 2 + rr;
        const float* p = base + (size_t)r * DDIM;
        float s = 0.f;
#pragma unroll
        for (int k = lane; k < DDIM; k += 32) { float v = p[k]; s = fmaf(v, v, s); }
#pragma unroll
        for (int off = 16; off; off >>= 1) s += __shfl_down_sync(0xffffffffu, s, off);
        if (lane == 0) { g_sq[r0 + r] = s; wsum += (double)s; }
    }
    if (lane == 0) ws[w] = wsum;
    __syncthreads();
    if (threadIdx.x == 0) {
        double t = 0.0;
#pragma unroll
        for (int i = 0; i < 8; i++) t += ws[i];
        g_p_sqsum[b] = t;
        __threadfence();
        last_sh = (atomicAdd(&g_done_prep, 1u) == PBLK - 1);
    }
    __syncthreads();

    if (!last_sh) return;
    // ---- last-arriving block: bandwidth ----
    __threadfence();
    const int t = threadIdx.x;
    float cs = 0.f;
#pragma unroll 8
    for (int bb = 0; bb < PBLK; bb++) cs += g_p_colf[bb][t];
    red[t] = (double)cs * (double)cs;
    __syncthreads();
    for (int off = 128; off; off >>= 1) {
        if (t < off) red[t] += red[t + off];
        __syncthreads();
    }
    double colsq = red[0];
    __syncthreads();
    double q = 0.0;
    for (int i = t; i < PBLK; i += 256) q += g_p_sqsum[i];
    red[t] = q;
    __syncthreads();
    for (int off = 128; off; off >>= 1) {
        if (t < off) red[t] += red[t + off];
        __syncthreads();
    }
    if (t == 0) {
        double n = (double)NROWS;
        double sumL2 = 2.0 * n * red[0] - 2.0 * colsq;
        double bw = sumL2 / (n * n - n) / 4.0;   // / KERNEL_MUL^(KERNEL_NUM//2)
        g_negc = (float)(-M_LOG2E / (16.0 * bw));
        g_done_prep = 0;                          // reset for next replay
    }
}

// ---------------------------------------------------------------------------
// k_main: 2080 CTAs, one upper-triangle 128x128 tile each; 3-stage ring.
__global__ __launch_bounds__(256, 2) void k_main(float* __restrict__ out) {
    const int u = blockIdx.x;
    int bi = (int)((2.0f * NTILE + 1.0f
                    - sqrtf((2.0f * NTILE + 1.0f) * (2.0f * NTILE + 1.0f)
                            - 8.0f * (float)u)) * 0.5f);
    while (bi > 0 && bi * NTILE - bi * (bi - 1) / 2 > u) bi--;
    while ((bi + 1) * NTILE - (bi + 1) * bi / 2 <= u) bi++;
    const int bj = bi + (u - (bi * NTILE - bi * (bi - 1) / 2));

    extern __shared__ __align__(16) char dsm[];
    __shared__ float  sqA[TB], sqB[TB];
    __shared__ double red[256];
    __shared__ int last_sh;

    const int t    = threadIdx.x;
    const int lane = t & 31;
    const int w    = t >> 5;
    const int wr   = w & 3;          // warp row block  (32 rows)
    const int wc   = w >> 2;         // warp col block  (64 cols)

    const uint32_t sbase = smem_addr_u32(dsm);

    if (t < TB)      sqA[t]      = g_sq[bi * TB + t];
    else             sqB[t - TB] = g_sq[bj * TB + (t - TB)];

    const size_t rowA = (size_t)bi * TB * DDIM;
    const size_t rowB = (size_t)bj * TB * DDIM;

    // staging lane constants: row = t>>2 (0..63), 16B unit = t&3
    const int crow = t >> 2, cun = t & 3;
    const uint32_t dst0 = swz_off(crow, cun);          // rows 0..63
    const uint32_t dst1 = dst0 + 64 * ROWB;            // rows 64..127 (same swz)
    const size_t   soff = (size_t)crow * DDIM + cun * 8;
    const __nv_bfloat16* srcT[4] = {g_hi + rowA + soff, g_lo + rowA + soff,
                                    g_hi + rowB + soff, g_lo + rowB + soff};

    // ldsm per-lane constant offsets (stage-relative, k16 step 0; step 1 = ^32)
    const int laneR = lane & 15, laneU = lane >> 4;
    uint32_t aoff[2][2], boff[2][2][2];
#pragma unroll
    for (int m = 0; m < 2; m++) {
        int r = wr * 32 + m * 16 + laneR;
        aoff[m][0] = 0 * TILEC + swz_off(r, laneU);   // Ahi
        aoff[m][1] = 1 * TILEC + swz_off(r, laneU);   // Alo
    }
#pragma unroll
    for (int h = 0; h < 2; h++)
#pragma unroll
        for (int s = 0; s < 2; s++) {
            int r = wc * 64 + h * 32 + s * 16 + laneR;
            boff[h][s][0] = 2 * TILEC + swz_off(r, laneU);   // Bhi
            boff[h][s][1] = 3 * TILEC + swz_off(r, laneU);   // Blo
        }

    float acc[2][8][4];
#pragma unroll
    for (int m = 0; m < 2; m++)
#pragma unroll
        for (int n = 0; n < 8; n++)
#pragma unroll
            for (int q = 0; q < 4; q++) acc[m][n][q] = 0.f;

#define STAGE(cc, slot)                                                       \
    do {                                                                      \
        const uint32_t sb_ = sbase + (uint32_t)((slot) * STAGEB);             \
        _Pragma("unroll")                                                     \
        for (int tl = 0; tl < 4; tl++) {                                      \
            const __nv_bfloat16* s_ = srcT[tl] + (cc) * CHUNK;                \
            cpasync16(sb_ + tl * TILEC + dst0, s_);                           \
            cpasync16(sb_ + tl * TILEC + dst1, s_ + 64 * DDIM);               \
        }                                                                     \
        asm volatile("cp.async.commit_group;" ::: "memory");                  \
    } while (0)

    // prologue: chunks 0, 1 in flight
    STAGE(0, 0); STAGE(1, 1);

    int slot_m = 0;   // slot of chunk c
    int slot_s = 2;   // slot for chunk c+2
#pragma unroll 1
    for (int c = 0; c < NCHUNK; c++) {
        if (c < NCHUNK - 1) asm volatile("cp.async.wait_group 1;" ::: "memory");
        else                asm volatile("cp.async.wait_group 0;" ::: "memory");
        __syncthreads();   // chunk c visible; all warps done reading chunk c-1
        if (c + 2 < NCHUNK) STAGE(c + 2, slot_s);

        const uint32_t sb = sbase + (uint32_t)(slot_m * STAGEB);
#pragma unroll
        for (int ks = 0; ks < 2; ks++) {
            const uint32_t kx = ks ? 32u : 0u;   // k16 step 1: addr ^ 32
            uint32_t ah[2][4], al[2][4];
#pragma unroll
            for (int m = 0; m < 2; m++) {
                ldsm4(sb + (aoff[m][0] ^ kx), ah[m]);
                ldsm4(sb + (aoff[m][1] ^ kx), al[m]);
            }
#pragma unroll
            for (int h = 0; h < 2; h++) {
                uint32_t bh[2][4], bl[2][4];
#pragma unroll
                for (int s = 0; s < 2; s++) {
                    ldsm4(sb + (boff[h][s][0] ^ kx), bh[s]);
                    ldsm4(sb + (boff[h][s][1] ^ kx), bl[s]);
                }
                // interleaved 3-pass (empirically best order, R8)
#pragma unroll
                for (int m = 0; m < 2; m++)
#pragma unroll
                    for (int s = 0; s < 2; s++)
#pragma unroll
                        for (int sub = 0; sub < 2; sub++) {
                            const int nb = h * 4 + s * 2 + sub;
                            mma16816(acc[m][nb], ah[m],
                                     bh[s][sub], bh[s][sub + 2]);  // hi*hi
                            mma16816(acc[m][nb], ah[m],
                                     bl[s][sub], bl[s][sub + 2]);  // hi*lo
                            mma16816(acc[m][nb], al[m],
                                     bh[s][sub], bh[s][sub + 2]);  // lo*hi
                        }
            }
        }
        slot_m = (slot_m == 2) ? 0 : slot_m + 1;
        slot_s = (slot_s == 2) ? 0 : slot_s + 1;
    }
#undef STAGE

    // ---- epilogue: 5-kernel sum per pair ----
    const float negc = g_negc;
    const int g  = lane >> 2;
    const int c2 = (lane & 3) * 2;
    float fsum = 0.f;
#pragma unroll
    for (int m = 0; m < 2; m++) {
        const int r0 = wr * 32 + m * 16 + g;
        const float s0 = sqA[r0], s1 = sqA[r0 + 8];
#pragma unroll
        for (int nb = 0; nb < 8; nb++) {
            const int cc = wc * 64 + nb * 8 + c2;
            const float t0 = sqB[cc], t1 = sqB[cc + 1];
#pragma unroll
            for (int q = 0; q < 4; q++) {
                const float sr = (q >= 2) ? s1 : s0;
                const float sc = (q & 1) ? t1 : t0;
                float L2 = fmaxf(sr + sc - 2.f * acc[m][nb][q], 0.f);
                float v;
                asm("ex2.approx.ftz.f32 %0, %1;" : "=f"(v) : "f"(L2 * negc));
                float v2 = v * v, v4 = v2 * v2, v8 = v4 * v4, v16 = v8 * v8;
                fsum += v + v2 + v4 + v8 + v16;
            }
        }
    }
    double sgnw = ((bi < 32) == (bj < 32)) ? 1.0 : -1.0;
    if (bj != bi) sgnw *= 2.0;
    red[t] = (double)fsum * sgnw;
    __syncthreads();
    for (int off = 128; off; off >>= 1) {
        if (t < off) red[t] += red[t + off];
        __syncthreads();
    }
    if (t == 0) {
        g_partial[u] = red[0];
        __threadfence();
        last_sh = (atomicAdd(&g_done_main, 1u) == NWORK - 1);
    }
    __syncthreads();

    if (!last_sh) return;
    // ---- last-arriving CTA: deterministic final reduction ----
    __threadfence();
    double s = 0.0;
    for (int i = t; i < NWORK; i += 256) s += g_partial[i];
    red[t] = s;
    __syncthreads();
    for (int off = 128; off; off >>= 1) {
        if (t < off) red[t] += red[t + off];
        __syncthreads();
    }
    if (t == 0) {
        out[0] = (float)(red[0] / ((double)NX * (double)NX));
        g_done_main = 0;                          // reset for next replay
    }
}

// ---------------------------------------------------------------------------
#define SMEM_DYN (NSTAGE * STAGEB)   // 98304 B -> 2 CTAs/SM

extern "C" void kernel_launch(void* const* d_in, const int* in_sizes, int n_in,
                              void* d_out, int out_size) {
    const float* x = (const float*)d_in[0];
    const float* y = (const float*)d_in[1];
    (void)in_sizes; (void)n_in; (void)out_size;

    k_prep<<<PBLK, 256>>>(x, y);
    cudaFuncSetAttribute(k_main, cudaFuncAttributeMaxDynamicSharedMemorySize, SMEM_DYN);
    k_main<<<NWORK, 256, SMEM_DYN>>>((float*)d_out);
}

// round 13
// speedup vs baseline: 1.5529x; 1.4742x over previous
#include <cuda_runtime.h>
#include <cuda_bf16.h>
#include <cstdint>
#include <math.h>

// MMDDistance on GB300 (sm_103 base target): 2-pass split-bf16 HMMA gram
// (G ~= x * bf16(x)^T via hi*hi + lo*hi), prepacked operands, R8 loop shape.
//
//  k_prep : fp32 -> (hi,lo) bf16 prepack + row sq norms + column sums;
//           last-arriving block computes bandwidth (g_negc)
//  k_main : one 128x128 upper-triangle tile per CTA; 4 K-chunks of 64,
//           cp.async staging of 3 tiles (Ahi, Alo, Bhi); 2-pass mma.sync;
//           epilogue: L2 -> one EX2 + 4 squarings -> signed partial;
//           last-arriving CTA does the deterministic final reduction.

#define NROWS 8192
#define NX    4096
#define DDIM  256
#define TB    128
#define NTILE 64
#define NWORK (NTILE * (NTILE + 1) / 2)   // 2080 upper-triangle tiles
#define CHUNK 64
#define NCHUNK (DDIM / CHUNK)              // 4
#define ROWB  128                          // smem row bytes (64 bf16, swizzled)
#define TILEB (TB * ROWB)                  // 16384 B per tile
#define PBLK  512                          // k_prep blocks (16 rows each)

__device__ __nv_bfloat16 g_hi[NROWS * DDIM];
__device__ __nv_bfloat16 g_lo[NROWS * DDIM];
__device__ float  g_sq[NROWS];
__device__ double g_p_sqsum[PBLK];
__device__ float  g_p_colf[PBLK][DDIM];
__device__ float  g_negc;                  // -log2(e)/(16*bandwidth)
__device__ double g_partial[NWORK];
__device__ unsigned int g_done_prep;       // zero-init; self-resetting
__device__ unsigned int g_done_main;       // zero-init; self-resetting

// ---------------------------------------------------------------- helpers
__device__ __forceinline__ uint32_t smem_addr_u32(const void* p) {
    uint32_t a;
    asm("{ .reg .u64 t; cvta.to.shared.u64 t, %1; cvt.u32.u64 %0, t; }"
        : "=r"(a) : "l"(p));
    return a;
}
__device__ __forceinline__ void ldsm4(uint32_t addr, uint32_t r[4]) {
    asm volatile("ldmatrix.sync.aligned.m8n8.x4.shared.b16 {%0,%1,%2,%3}, [%4];"
                 : "=r"(r[0]), "=r"(r[1]), "=r"(r[2]), "=r"(r[3]) : "r"(addr));
}
__device__ __forceinline__ void mma16816(float d[4], const uint32_t a[4],
                                         uint32_t b0, uint32_t b1) {
    asm volatile(
        "mma.sync.aligned.m16n8k16.row.col.f32.bf16.bf16.f32 "
        "{%0,%1,%2,%3}, {%4,%5,%6,%7}, {%8,%9}, {%0,%1,%2,%3};"
        : "+f"(d[0]), "+f"(d[1]), "+f"(d[2]), "+f"(d[3])
        : "r"(a[0]), "r"(a[1]), "r"(a[2]), "r"(a[3]), "r"(b0), "r"(b1));
}
__device__ __forceinline__ void cpasync16(uint32_t dst, const void* src) {
    asm volatile("cp.async.ca.shared.global [%0], [%1], 16;"
                 :: "r"(dst), "l"(src) : "memory");
}
// swizzled ldmatrix x4 address: logical (row, k) with k multiple of 8.
// smem layout: byte = row*128 + ((unit ^ (row & 7)) << 4), unit = k>>3.
__device__ __forceinline__ uint32_t lm_addr(uint32_t base, int row0, int k0,
                                            int lane) {
    int r = row0 + (lane & 15);
    int u = (k0 >> 3) + (lane >> 4);
    u ^= (r & 7);
    return base + (uint32_t)(r * ROWB + (u << 4));
}

// ---------------------------------------------------------------------------
// k_prep: PBLK blocks x 256 thr; block b covers rows [16b, 16b+16).
__global__ __launch_bounds__(256) void k_prep(const float* __restrict__ x,
                                              const float* __restrict__ y) {
    const int b = blockIdx.x, r0 = b * 16;
    const int w = threadIdx.x >> 5, lane = threadIdx.x & 31;
    __shared__ double ws[8];
    __shared__ double red[256];
    __shared__ int last_sh;

    const float* base = (r0 < NX) ? (x + (size_t)r0 * DDIM)
                                  : (y + (size_t)(r0 - NX) * DDIM);

    // conversion + column partials: thread owns column k over 16 rows
    {
        const int k = threadIdx.x;
        float acc = 0.f;
#pragma unroll
        for (int i = 0; i < 16; i++) {
            float v = base[(size_t)i * DDIM + k];
            __nv_bfloat16 h = __float2bfloat16_rn(v);
            float l = v - __bfloat162float(h);
            size_t idx = (size_t)(r0 + i) * DDIM + k;
            g_hi[idx] = h;
            g_lo[idx] = __float2bfloat16_rn(l);
            acc += v;
        }
        g_p_colf[b][k] = acc;
    }

    // row squared norms (cache-hot)
    double wsum = 0.0;
#pragma unroll
    for (int rr = 0; rr < 2; rr++) {
        int r = w * 2 + rr;
        const float* p = base + (size_t)r * DDIM;
        float s = 0.f;
#pragma unroll
        for (int k = lane; k < DDIM; k += 32) { float v = p[k]; s = fmaf(v, v, s); }
#pragma unroll
        for (int off = 16; off; off >>= 1) s += __shfl_down_sync(0xffffffffu, s, off);
        if (lane == 0) { g_sq[r0 + r] = s; wsum += (double)s; }
    }
    if (lane == 0) ws[w] = wsum;
    __syncthreads();
    if (threadIdx.x == 0) {
        double t = 0.0;
#pragma unroll
        for (int i = 0; i < 8; i++) t += ws[i];
        g_p_sqsum[b] = t;
        __threadfence();
        last_sh = (atomicAdd(&g_done_prep, 1u) == PBLK - 1);
    }
    __syncthreads();

    if (!last_sh) return;
    // ---- last-arriving block: bandwidth ----
    __threadfence();
    const int t = threadIdx.x;
    float cs = 0.f;
#pragma unroll 8
    for (int bb = 0; bb < PBLK; bb++) cs += g_p_colf[bb][t];
    red[t] = (double)cs * (double)cs;
    __syncthreads();
    for (int off = 128; off; off >>= 1) {
        if (t < off) red[t] += red[t + off];
        __syncthreads();
    }
    double colsq = red[0];
    __syncthreads();
    double q = 0.0;
    for (int i = t; i < PBLK; i += 256) q += g_p_sqsum[i];
    red[t] = q;
    __syncthreads();
    for (int off = 128; off; off >>= 1) {
        if (t < off) red[t] += red[t + off];
        __syncthreads();
    }
    if (t == 0) {
        double n = (double)NROWS;
        double sumL2 = 2.0 * n * red[0] - 2.0 * colsq;
        double bw = sumL2 / (n * n - n) / 4.0;   // / KERNEL_MUL^(KERNEL_NUM//2)
        g_negc = (float)(-M_LOG2E / (16.0 * bw));
        g_done_prep = 0;                          // reset for next replay
    }
}

// ---------------------------------------------------------------------------
// k_main: 2080 CTAs, one upper-triangle 128x128 tile each. R8 loop shape,
// 3 staged tiles (Ahi, Alo, Bhi), 2-pass MMA.
__global__ __launch_bounds__(256, 2) void k_main(float* __restrict__ out) {
    const int u = blockIdx.x;
    int bi = (int)((2.0f * NTILE + 1.0f
                    - sqrtf((2.0f * NTILE + 1.0f) * (2.0f * NTILE + 1.0f)
                            - 8.0f * (float)u)) * 0.5f);
    while (bi > 0 && bi * NTILE - bi * (bi - 1) / 2 > u) bi--;
    while ((bi + 1) * NTILE - (bi + 1) * bi / 2 <= u) bi++;
    const int bj = bi + (u - (bi * NTILE - bi * (bi - 1) / 2));

    extern __shared__ __align__(16) char dsm[];
    __shared__ float  sqA[TB], sqB[TB];
    __shared__ double red[256];
    __shared__ int last_sh;

    const int t    = threadIdx.x;
    const int lane = t & 31;
    const int w    = t >> 5;
    const int wr   = w & 3;          // warp row block  (32 rows)
    const int wc   = w >> 2;         // warp col block  (64 cols)

    const uint32_t sbase = smem_addr_u32(dsm);
    const uint32_t uT[3] = {sbase, sbase + TILEB, sbase + 2 * TILEB};
                         // Ahi, Alo, Bhi

    if (t < TB)      sqA[t]      = g_sq[bi * TB + t];
    else             sqB[t - TB] = g_sq[bj * TB + (t - TB)];

    const size_t rowA = (size_t)bi * TB * DDIM;
    const size_t rowB = (size_t)bj * TB * DDIM;
    const __nv_bfloat16* srcT[3] = {g_hi + rowA, g_lo + rowA, g_hi + rowB};

    float acc[2][8][4];
#pragma unroll
    for (int m = 0; m < 2; m++)
#pragma unroll
        for (int n = 0; n < 8; n++)
#pragma unroll
            for (int q = 0; q < 4; q++) acc[m][n][q] = 0.f;

    const int crow = t >> 3;   // 0..31: staging row base
    const int cun  = t & 7;    // 16B unit within 128B row

    for (int c = 0; c < NCHUNK; c++) {
        const int kt = c * CHUNK;
        __syncthreads();       // previous chunk's readers are done
#pragma unroll
        for (int tl = 0; tl < 3; tl++) {
            const __nv_bfloat16* src = srcT[tl] + kt + cun * 8;
#pragma unroll
            for (int i = 0; i < 4; i++) {
                int r = crow + i * 32;
                uint32_t dst = uT[tl] + (uint32_t)(r * ROWB
                             + ((cun ^ (r & 7)) << 4));
                cpasync16(dst, src + (size_t)r * DDIM);
            }
        }
        asm volatile("cp.async.commit_group;" ::: "memory");
        asm volatile("cp.async.wait_group 0;" ::: "memory");
        __syncthreads();

        // ---- MMA over this chunk: 4 k16 steps, 2 passes ----
#pragma unroll
        for (int ks = 0; ks < CHUNK / 16; ks++) {
            const int k0 = ks * 16;
            uint32_t ah[2][4], al[2][4];
#pragma unroll
            for (int m = 0; m < 2; m++) {
                int row0 = wr * 32 + m * 16;
                ldsm4(lm_addr(uT[0], row0, k0, lane), ah[m]);
                ldsm4(lm_addr(uT[1], row0, k0, lane), al[m]);
            }
#pragma unroll
            for (int h = 0; h < 2; h++) {      // column halves of 32
                uint32_t bh[2][4];
#pragma unroll
                for (int s = 0; s < 2; s++) {  // two n16 blocks
                    int n0 = wc * 64 + h * 32 + s * 16;
                    ldsm4(lm_addr(uT[2], n0, k0, lane), bh[s]);
                }
#pragma unroll
                for (int m = 0; m < 2; m++)
#pragma unroll
                    for (int s = 0; s < 2; s++)
#pragma unroll
                        for (int sub = 0; sub < 2; sub++) {
                            const int nb = h * 4 + s * 2 + sub;
                            mma16816(acc[m][nb], ah[m],
                                     bh[s][sub], bh[s][sub + 2]);  // hi*hi
                            mma16816(acc[m][nb], al[m],
                                     bh[s][sub], bh[s][sub + 2]);  // lo*hi
                        }
            }
        }
    }

    // ---- epilogue: 5-kernel sum per pair ----
    const float negc = g_negc;
    const int g  = lane >> 2;
    const int c2 = (lane & 3) * 2;
    float fsum = 0.f;
#pragma unroll
    for (int m = 0; m < 2; m++) {
        const int r0 = wr * 32 + m * 16 + g;
        const float s0 = sqA[r0], s1 = sqA[r0 + 8];
#pragma unroll
        for (int nb = 0; nb < 8; nb++) {
            const int cc = wc * 64 + nb * 8 + c2;
            const float t0 = sqB[cc], t1 = sqB[cc + 1];
#pragma unroll
            for (int q = 0; q < 4; q++) {
                const float sr = (q >= 2) ? s1 : s0;
                const float sc = (q & 1) ? t1 : t0;
                float L2 = fmaxf(sr + sc - 2.f * acc[m][nb][q], 0.f);
                float v;
                asm("ex2.approx.ftz.f32 %0, %1;" : "=f"(v) : "f"(L2 * negc));
                float v2 = v * v, v4 = v2 * v2, v8 = v4 * v4, v16 = v8 * v8;
                fsum += v + v2 + v4 + v8 + v16;
            }
        }
    }
    double sgnw = ((bi < 32) == (bj < 32)) ? 1.0 : -1.0;
    if (bj != bi) sgnw *= 2.0;
    red[t] = (double)fsum * sgnw;
    __syncthreads();
    for (int off = 128; off; off >>= 1) {
        if (t < off) red[t] += red[t + off];
        __syncthreads();
    }
    if (t == 0) {
        g_partial[u] = red[0];
        __threadfence();
        last_sh = (atomicAdd(&g_done_main, 1u) == NWORK - 1);
    }
    __syncthreads();

    if (!last_sh) return;
    // ---- last-arriving CTA: deterministic final reduction ----
    __threadfence();
    double s = 0.0;
    for (int i = t; i < NWORK; i += 256) s += g_partial[i];
    red[t] = s;
    __syncthreads();
    for (int off = 128; off; off >>= 1) {
        if (t < off) red[t] += red[t + off];
        __syncthreads();
    }
    if (t == 0) {
        out[0] = (float)(red[0] / ((double)NX * (double)NX));
        g_done_main = 0;                          // reset for next replay
    }
}

// ---------------------------------------------------------------------------
#define SMEM_DYN (3 * TILEB)   // 49152 B -> 2 CTAs/SM (regs bound anyway)

extern "C" void kernel_launch(void* const* d_in, const int* in_sizes, int n_in,
                              void* d_out, int out_size) {
    const float* x = (const float*)d_in[0];
    const float* y = (const float*)d_in[1];
    (void)in_sizes; (void)n_in; (void)out_size;

    k_prep<<<PBLK, 256>>>(x, y);
    cudaFuncSetAttribute(k_main, cudaFuncAttributeMaxDynamicSharedMemorySize, SMEM_DYN);
    k_main<<<NWORK, 256, SMEM_DYN>>>((float*)d_out);
}

// round 15
// speedup vs baseline: 2.1300x; 1.3716x over previous
#include <cuda_runtime.h>
#include <cuda_fp16.h>
#include <cstdint>
#include <math.h>

// MMDDistance on GB300 (sm_103 base target): single-pass fp16 HMMA gram
// (G ~= fp16(x) * fp16(x)^T, fp32 accumulate), prepacked fp16 operands.
//
//  k_prep : fp32 -> fp16 prepack + row sq norms + column sums;
//           last-arriving block computes bandwidth (g_negc)
//  k_main : one 128x128 upper-triangle tile per CTA; 4 K-chunks of 64,
//           cp.async staging of 2 tiles (Ah, Bh); 1-pass mma.sync fp16;
//           epilogue: L2 -> one EX2 + 4 squarings -> signed partial;
//           last-arriving CTA does the deterministic final reduction.

#define NROWS 8192
#define NX    4096
#define DDIM  256
#define TB    128
#define NTILE 64
#define NWORK (NTILE * (NTILE + 1) / 2)   // 2080 upper-triangle tiles
#define CHUNK 64
#define NCHUNK (DDIM / CHUNK)              // 4
#define ROWB  128                          // smem row bytes (64 fp16, swizzled)
#define TILEB (TB * ROWB)                  // 16384 B per tile
#define PBLK  512                          // k_prep blocks (16 rows each)

__device__ __half  g_h[NROWS * DDIM];
__device__ float  g_sq[NROWS];
__device__ double g_p_sqsum[PBLK];
__device__ float  g_p_colf[PBLK][DDIM];
__device__ float  g_negc;                  // -log2(e)/(16*bandwidth)
__device__ double g_partial[NWORK];
__device__ unsigned int g_done_prep;       // zero-init; self-resetting
__device__ unsigned int g_done_main;       // zero-init; self-resetting

// ---------------------------------------------------------------- helpers
__device__ __forceinline__ uint32_t smem_addr_u32(const void* p) {
    uint32_t a;
    asm("{ .reg .u64 t; cvta.to.shared.u64 t, %1; cvt.u32.u64 %0, t; }"
        : "=r"(a) : "l"(p));
    return a;
}
__device__ __forceinline__ void ldsm4(uint32_t addr, uint32_t r[4]) {
    asm volatile("ldmatrix.sync.aligned.m8n8.x4.shared.b16 {%0,%1,%2,%3}, [%4];"
                 : "=r"(r[0]), "=r"(r[1]), "=r"(r[2]), "=r"(r[3]) : "r"(addr));
}
__device__ __forceinline__ void mma16816(float d[4], const uint32_t a[4],
                                         uint32_t b0, uint32_t b1) {
    asm volatile(
        "mma.sync.aligned.m16n8k16.row.col.f32.f16.f16.f32 "
        "{%0,%1,%2,%3}, {%4,%5,%6,%7}, {%8,%9}, {%0,%1,%2,%3};"
        : "+f"(d[0]), "+f"(d[1]), "+f"(d[2]), "+f"(d[3])
        : "r"(a[0]), "r"(a[1]), "r"(a[2]), "r"(a[3]), "r"(b0), "r"(b1));
}
__device__ __forceinline__ void cpasync16(uint32_t dst, const void* src) {
    asm volatile("cp.async.ca.shared.global [%0], [%1], 16;"
                 :: "r"(dst), "l"(src) : "memory");
}
// swizzled smem: byte = row*128 + ((unit ^ (row & 7)) << 4), unit = k>>3.
__device__ __forceinline__ uint32_t swz_off(int r, int u) {
    return (uint32_t)(r * ROWB + (((u ^ r) & 7) << 4) + ((u >> 3) << 7));
}
// ldsm x4 base address at k0=0; k-step ks applies addr ^ (32*ks)
// (valid: unit du=2*ks XORs bits 1-2 of the 3-bit unit field).
__device__ __forceinline__ uint32_t lm_base(uint32_t tile_off, int row0, int lane) {
    int r = row0 + (lane & 15);
    int u = lane >> 4;                     // 0 or 1
    return tile_off + (uint32_t)(r * ROWB + (((u ^ r) & 7) << 4));
}

// ---------------------------------------------------------------------------
// k_prep: PBLK blocks x 256 thr; block b covers rows [16b, 16b+16).
__global__ __launch_bounds__(256) void k_prep(const float* __restrict__ x,
                                              const float* __restrict__ y) {
    const int b = blockIdx.x, r0 = b * 16;
    const int w = threadIdx.x >> 5, lane = threadIdx.x & 31;
    __shared__ double ws[8];
    __shared__ double red[256];
    __shared__ int last_sh;

    const float* base = (r0 < NX) ? (x + (size_t)r0 * DDIM)
                                  : (y + (size_t)(r0 - NX) * DDIM);

    // conversion + column partials: thread owns column k over 16 rows
    {
        const int k = threadIdx.x;
        float acc = 0.f;
#pragma unroll
        for (int i = 0; i < 16; i++) {
            float v = base[(size_t)i * DDIM + k];
            g_h[(size_t)(r0 + i) * DDIM + k] = __float2half_rn(v);
            acc += v;
        }
        g_p_colf[b][k] = acc;
    }

    // row squared norms (cache-hot)
    double wsum = 0.0;
#pragma unroll
    for (int rr = 0; rr < 2; rr++) {
        int r = w * 2 + rr;
        const float* p = base + (size_t)r * DDIM;
        float s = 0.f;
#pragma unroll
        for (int k = lane; k < DDIM; k += 32) { float v = p[k]; s = fmaf(v, v, s); }
#pragma unroll
        for (int off = 16; off; off >>= 1) s += __shfl_down_sync(0xffffffffu, s, off);
        if (lane == 0) { g_sq[r0 + r] = s; wsum += (double)s; }
    }
    if (lane == 0) ws[w] = wsum;
    __syncthreads();
    if (threadIdx.x == 0) {
        double t = 0.0;
#pragma unroll
        for (int i = 0; i < 8; i++) t += ws[i];
        g_p_sqsum[b] = t;
        __threadfence();
        last_sh = (atomicAdd(&g_done_prep, 1u) == PBLK - 1);
    }
    __syncthreads();

    if (!last_sh) return;
    // ---- last-arriving block: bandwidth ----
    __threadfence();
    const int t = threadIdx.x;
    float cs = 0.f;
#pragma unroll 8
    for (int bb = 0; bb < PBLK; bb++) cs += g_p_colf[bb][t];
    red[t] = (double)cs * (double)cs;
    __syncthreads();
    for (int off = 128; off; off >>= 1) {
        if (t < off) red[t] += red[t + off];
        __syncthreads();
    }
    double colsq = red[0];
    __syncthreads();
    double q = 0.0;
    for (int i = t; i < PBLK; i += 256) q += g_p_sqsum[i];
    red[t] = q;
    __syncthreads();
    for (int off = 128; off; off >>= 1) {
        if (t < off) red[t] += red[t + off];
        __syncthreads();
    }
    if (t == 0) {
        double n = (double)NROWS;
        double sumL2 = 2.0 * n * red[0] - 2.0 * colsq;
        double bw = sumL2 / (n * n - n) / 4.0;   // / KERNEL_MUL^(KERNEL_NUM//2)
        g_negc = (float)(-M_LOG2E / (16.0 * bw));
        g_done_prep = 0;                          // reset for next replay
    }
}

// ---------------------------------------------------------------------------
// k_main: 2080 CTAs, one upper-triangle 128x128 tile each. R8 loop shape,
// 2 staged tiles (Ah, Bh), single-pass fp16 MMA.
__global__ __launch_bounds__(256, 2) void k_main(float* __restrict__ out) {
    const int u = blockIdx.x;
    int bi = (int)((2.0f * NTILE + 1.0f
                    - sqrtf((2.0f * NTILE + 1.0f) * (2.0f * NTILE + 1.0f)
                            - 8.0f * (float)u)) * 0.5f);
    while (bi > 0 && bi * NTILE - bi * (bi - 1) / 2 > u) bi--;
    while ((bi + 1) * NTILE - (bi + 1) * bi / 2 <= u) bi++;
    const int bj = bi + (u - (bi * NTILE - bi * (bi - 1) / 2));

    extern __shared__ __align__(16) char dsm[];
    __shared__ float  sqA[TB], sqB[TB];
    __shared__ double red[256];
    __shared__ int last_sh;

    const int t    = threadIdx.x;
    const int lane = t & 31;
    const int w    = t >> 5;
    const int wr   = w & 3;          // warp row block  (32 rows)
    const int wc   = w >> 2;         // warp col block  (64 cols)

    const uint32_t sbase = smem_addr_u32(dsm);
    const uint32_t uA = sbase, uB = sbase + TILEB;

    if (t < TB)      sqA[t]      = g_sq[bi * TB + t];
    else             sqB[t - TB] = g_sq[bj * TB + (t - TB)];

    const __half* srcA = g_h + (size_t)bi * TB * DDIM;
    const __half* srcB = g_h + (size_t)bj * TB * DDIM;

    // ldsm per-lane base offsets (k-step ks -> ^ (32*ks))
    uint32_t aoff[2], boff[2][2];
#pragma unroll
    for (int m = 0; m < 2; m++)
        aoff[m] = lm_base(0, wr * 32 + m * 16, lane);           // Ah tile
#pragma unroll
    for (int h = 0; h < 2; h++)
#pragma unroll
        for (int s = 0; s < 2; s++)
            boff[h][s] = lm_base(TILEB, wc * 64 + h * 32 + s * 16, lane);

    float acc[2][8][4];
#pragma unroll
    for (int m = 0; m < 2; m++)
#pragma unroll
        for (int n = 0; n < 8; n++)
#pragma unroll
            for (int q = 0; q < 4; q++) acc[m][n][q] = 0.f;

    const int crow = t >> 3;   // 0..31: staging row base
    const int cun  = t & 7;    // 16B unit within 128B row
    const uint32_t cdst = (uint32_t)(crow * ROWB + (((cun ^ crow) & 7) << 4));
    const size_t   csrc = (size_t)crow * DDIM + cun * 8;

    for (int c = 0; c < NCHUNK; c++) {
        const int kt = c * CHUNK;
        __syncthreads();       // previous chunk's readers are done
#pragma unroll
        for (int i = 0; i < 4; i++) {
            // rows r = crow + 32*i: swz term (cun^r)&7 == (cun^crow)&7 ^ 0 (32i keeps low 3 bits)
            uint32_t d = cdst + (uint32_t)(i * 32 * ROWB);
            size_t   s = csrc + (size_t)(i * 32) * DDIM + kt;
            cpasync16(uA + d, srcA + s);
            cpasync16(uB + d, srcB + s);
        }
        asm volatile("cp.async.commit_group;" ::: "memory");
        asm volatile("cp.async.wait_group 0;" ::: "memory");
        __syncthreads();

        // ---- MMA over this chunk: 4 k16 steps, single fp16 pass ----
#pragma unroll
        for (int ks = 0; ks < CHUNK / 16; ks++) {
            const uint32_t kx = (uint32_t)(ks * 32);
            uint32_t ah[2][4];
#pragma unroll
            for (int m = 0; m < 2; m++) ldsm4((uA + 0) + (aoff[m] ^ kx), ah[m]);
#pragma unroll
            for (int h = 0; h < 2; h++) {
                uint32_t bh[2][4];
#pragma unroll
                for (int s = 0; s < 2; s++)
                    ldsm4(sbase + (boff[h][s] ^ kx), bh[s]);
#pragma unroll
                for (int m = 0; m < 2; m++)
#pragma unroll
                    for (int s = 0; s < 2; s++)
#pragma unroll
                        for (int sub = 0; sub < 2; sub++)
                            mma16816(acc[m][h * 4 + s * 2 + sub], ah[m],
                                     bh[s][sub], bh[s][sub + 2]);
            }
        }
    }

    // ---- epilogue: 5-kernel sum per pair ----
    const float negc = g_negc;
    const int g  = lane >> 2;
    const int c2 = (lane & 3) * 2;
    float fsum = 0.f;
#pragma unroll
    for (int m = 0; m < 2; m++) {
        const int r0 = wr * 32 + m * 16 + g;
        const float s0 = sqA[r0], s1 = sqA[r0 + 8];
#pragma unroll
        for (int nb = 0; nb < 8; nb++) {
            const int cc = wc * 64 + nb * 8 + c2;
            const float t0 = sqB[cc], t1 = sqB[cc + 1];
#pragma unroll
            for (int q = 0; q < 4; q++) {
                const float sr = (q >= 2) ? s1 : s0;
                const float sc = (q & 1) ? t1 : t0;
                float L2 = fmaxf(sr + sc - 2.f * acc[m][nb][q], 0.f);
                float v;
                asm("ex2.approx.ftz.f32 %0, %1;" : "=f"(v) : "f"(L2 * negc));
                float v2 = v * v, v4 = v2 * v2, v8 = v4 * v4, v16 = v8 * v8;
                fsum += v + v2 + v4 + v8 + v16;
            }
        }
    }
    double sgnw = ((bi < 32) == (bj < 32)) ? 1.0 : -1.0;
    if (bj != bi) sgnw *= 2.0;
    red[t] = (double)fsum * sgnw;
    __syncthreads();
    for (int off = 128; off; off >>= 1) {
        if (t < off) red[t] += red[t + off];
        __syncthreads();
    }
    if (t == 0) {
        g_partial[u] = red[0];
        __threadfence();
        last_sh = (atomicAdd(&g_done_main, 1u) == NWORK - 1);
    }
    __syncthreads();

    if (!last_sh) return;
    // ---- last-arriving CTA: deterministic final reduction ----
    __threadfence();
    double s = 0.0;
    for (int i = t; i < NWORK; i += 256) s += g_partial[i];
    red[t] = s;
    __syncthreads();
    for (int off = 128; off; off >>= 1) {
        if (t < off) red[t] += red[t + off];
        __syncthreads();
    }
    if (t == 0) {
        out[0] = (float)(red[0] / ((double)NX * (double)NX));
        g_done_main = 0;                          // reset for next replay
    }
}

// ---------------------------------------------------------------------------
#define SMEM_DYN (2 * TILEB)   // 32768 B -> 2 CTAs/SM (regs-bound)

extern "C" void kernel_launch(void* const* d_in, const int* in_sizes, int n_in,
                              void* d_out, int out_size) {
    const float* x = (const float*)d_in[0];
    const float* y = (const float*)d_in[1];
    (void)in_sizes; (void)n_in; (void)out_size;

    k_prep<<<PBLK, 256>>>(x, y);
    cudaFuncSetAttribute(k_main, cudaFuncAttributeMaxDynamicSharedMemorySize, SMEM_DYN);
    k_main<<<NWORK, 256, SMEM_DYN>>>((float*)d_out);
}

// round 16
// speedup vs baseline: 2.6575x; 1.2477x over previous
#include <cuda_runtime.h>
#include <cuda_fp16.h>
#include <cstdint>
#include <math.h>

// MMDDistance on GB300 (sm_103 base target): single-pass fp16 HMMA gram,
// prepacked fp16, 2-stage double buffer at CHUNK=64 (R8 event count).
//
//  k_prep : fp32 -> fp16 prepack + row sq norms; column sums and sq-sum
//           accumulated via atomics; last-arriving block computes g_negc
//  k_main : one 128x128 upper-triangle tile per CTA; 4 K-chunks of 64,
//           2-stage cp.async ring (chunk c+1 in flight under MMA of c);
//           epilogue: L2 -> one EX2 + 4 squarings -> signed partial;
//           last-arriving CTA does the final reduction.

#define NROWS 8192
#define NX    4096
#define DDIM  256
#define TB    128
#define NTILE 64
#define NWORK (NTILE * (NTILE + 1) / 2)   // 2080 upper-triangle tiles
#define CHUNK 64
#define NCHUNK (DDIM / CHUNK)              // 4
#define ROWB  128                          // smem row bytes (64 fp16, swizzled)
#define TILEB (TB * ROWB)                  // 16384 B per tile
#define BUFB  (2 * TILEB)                  // 32768 B per stage (Ah, Bh)
#define PBLK  512                          // k_prep blocks (16 rows each)

__device__ __half  g_h[NROWS * DDIM];
__device__ float  g_sq[NROWS];
__device__ float  g_colsumf[DDIM];         // atomic accum; self-resetting
__device__ double g_sqsum;                 // atomic accum; self-resetting
__device__ float  g_negc;                  // -log2(e)/(16*bandwidth)
__device__ double g_partial[NWORK];
__device__ unsigned int g_done_prep;       // zero-init; self-resetting
__device__ unsigned int g_done_main;       // zero-init; self-resetting

// ---------------------------------------------------------------- helpers
__device__ __forceinline__ uint32_t smem_addr_u32(const void* p) {
    uint32_t a;
    asm("{ .reg .u64 t; cvta.to.shared.u64 t, %1; cvt.u32.u64 %0, t; }"
        : "=r"(a) : "l"(p));
    return a;
}
__device__ __forceinline__ void ldsm4(uint32_t addr, uint32_t r[4]) {
    asm volatile("ldmatrix.sync.aligned.m8n8.x4.shared.b16 {%0,%1,%2,%3}, [%4];"
                 : "=r"(r[0]), "=r"(r[1]), "=r"(r[2]), "=r"(r[3]) : "r"(addr));
}
__device__ __forceinline__ void mma16816(float d[4], const uint32_t a[4],
                                         uint32_t b0, uint32_t b1) {
    asm volatile(
        "mma.sync.aligned.m16n8k16.row.col.f32.f16.f16.f32 "
        "{%0,%1,%2,%3}, {%4,%5,%6,%7}, {%8,%9}, {%0,%1,%2,%3};"
        : "+f"(d[0]), "+f"(d[1]), "+f"(d[2]), "+f"(d[3])
        : "r"(a[0]), "r"(a[1]), "r"(a[2]), "r"(a[3]), "r"(b0), "r"(b1));
}
__device__ __forceinline__ void cpasync16(uint32_t dst, const void* src) {
    asm volatile("cp.async.ca.shared.global [%0], [%1], 16;"
                 :: "r"(dst), "l"(src) : "memory");
}
// ldsm x4 base address at k0=0 (stage-relative); k-step ks applies ^ (32*ks).
__device__ __forceinline__ uint32_t lm_base(uint32_t tile_off, int row0, int lane) {
    int r = row0 + (lane & 15);
    int u = lane >> 4;                     // 0 or 1
    return tile_off + (uint32_t)(r * ROWB + (((u ^ r) & 7) << 4));
}

// ---------------------------------------------------------------------------
// k_prep: PBLK blocks x 256 thr; block b covers rows [16b, 16b+16).
__global__ __launch_bounds__(256) void k_prep(const float* __restrict__ x,
                                              const float* __restrict__ y) {
    const int b = blockIdx.x, r0 = b * 16;
    const int w = threadIdx.x >> 5, lane = threadIdx.x & 31;
    __shared__ double ws[8];
    __shared__ double red[256];
    __shared__ int last_sh;

    const float* base = (r0 < NX) ? (x + (size_t)r0 * DDIM)
                                  : (y + (size_t)(r0 - NX) * DDIM);

    // conversion + column partial: thread owns column k over 16 rows
    {
        const int k = threadIdx.x;
        float acc = 0.f;
#pragma unroll
        for (int i = 0; i < 16; i++) {
            float v = base[(size_t)i * DDIM + k];
            g_h[(size_t)(r0 + i) * DDIM + k] = __float2half_rn(v);
            acc += v;
        }
        atomicAdd(&g_colsumf[k], acc);
    }

    // row squared norms (cache-hot re-read)
    double wsum = 0.0;
#pragma unroll
    for (int rr = 0; rr < 2; rr++) {
        int r = w * 2 + rr;
        const float* p = base + (size_t)r * DDIM;
        float s = 0.f;
#pragma unroll
        for (int k = lane; k < DDIM; k += 32) { float v = p[k]; s = fmaf(v, v, s); }
#pragma unroll
        for (int off = 16; off; off >>= 1) s += __shfl_down_sync(0xffffffffu, s, off);
        if (lane == 0) { g_sq[r0 + r] = s; wsum += (double)s; }
    }
    if (lane == 0) ws[w] = wsum;
    __syncthreads();
    if (threadIdx.x == 0) {
        double t = 0.0;
#pragma unroll
        for (int i = 0; i < 8; i++) t += ws[i];
        atomicAdd(&g_sqsum, t);
        __threadfence();
        last_sh = (atomicAdd(&g_done_prep, 1u) == PBLK - 1);
    }
    __syncthreads();

    if (!last_sh) return;
    // ---- last-arriving block: bandwidth ----
    __threadfence();
    const int t = threadIdx.x;
    float cs = g_colsumf[t];
    red[t] = (double)cs * (double)cs;
    __syncthreads();
    for (int off = 128; off; off >>= 1) {
        if (t < off) red[t] += red[t + off];
        __syncthreads();
    }
    if (t == 0) {
        double n = (double)NROWS;
        double sumL2 = 2.0 * n * g_sqsum - 2.0 * red[0];
        double bw = sumL2 / (n * n - n) / 4.0;   // / KERNEL_MUL^(KERNEL_NUM//2)
        g_negc = (float)(-M_LOG2E / (16.0 * bw));
        g_sqsum = 0.0;                            // reset for next replay
        g_done_prep = 0;
    }
    g_colsumf[t] = 0.f;                           // reset for next replay
}

// ---------------------------------------------------------------------------
// k_main: 2080 CTAs, one upper-triangle 128x128 tile each; 2-stage ring
// at CHUNK=64 (same barrier/wait count as the proven single-buffer loop).
__global__ __launch_bounds__(256, 2) void k_main(float* __restrict__ out) {
    const int u = blockIdx.x;
    int bi = (int)((2.0f * NTILE + 1.0f
                    - sqrtf((2.0f * NTILE + 1.0f) * (2.0f * NTILE + 1.0f)
                            - 8.0f * (float)u)) * 0.5f);
    while (bi > 0 && bi * NTILE - bi * (bi - 1) / 2 > u) bi--;
    while ((bi + 1) * NTILE - (bi + 1) * bi / 2 <= u) bi++;
    const int bj = bi + (u - (bi * NTILE - bi * (bi - 1) / 2));

    extern __shared__ __align__(16) char dsm[];
    __shared__ float  sqA[TB], sqB[TB];
    __shared__ double red[256];
    __shared__ double wred[8];
    __shared__ int last_sh;

    const int t    = threadIdx.x;
    const int lane = t & 31;
    const int w    = t >> 5;
    const int wr   = w & 3;          // warp row block  (32 rows)
    const int wc   = w >> 2;         // warp col block  (64 cols)

    const uint32_t sbase = smem_addr_u32(dsm);

    if (t < TB)      sqA[t]      = g_sq[bi * TB + t];
    else             sqB[t - TB] = g_sq[bj * TB + (t - TB)];

    const __half* srcA = g_h + (size_t)bi * TB * DDIM;
    const __half* srcB = g_h + (size_t)bj * TB * DDIM;

    // ldsm per-lane base offsets relative to stage base (k-step -> ^ 32*ks)
    uint32_t aoff[2], boff[2][2];
#pragma unroll
    for (int m = 0; m < 2; m++)
        aoff[m] = lm_base(0, wr * 32 + m * 16, lane);            // A tile
#pragma unroll
    for (int h = 0; h < 2; h++)
#pragma unroll
        for (int s = 0; s < 2; s++)
            boff[h][s] = lm_base(TILEB, wc * 64 + h * 32 + s * 16, lane);

    float acc[2][8][4];
#pragma unroll
    for (int m = 0; m < 2; m++)
#pragma unroll
        for (int n = 0; n < 8; n++)
#pragma unroll
            for (int q = 0; q < 4; q++) acc[m][n][q] = 0.f;

    const int crow = t >> 3;   // 0..31: staging row base
    const int cun  = t & 7;    // 16B unit within 128B row
    const uint32_t cdst = (uint32_t)(crow * ROWB + (((cun ^ crow) & 7) << 4));
    const __half* sA0 = srcA + (size_t)crow * DDIM + cun * 8;
    const __half* sB0 = srcB + (size_t)crow * DDIM + cun * 8;

#define STAGE(cc)                                                             \
    do {                                                                      \
        const uint32_t bb_ = sbase + (uint32_t)(((cc) & 1) * BUFB);           \
        _Pragma("unroll")                                                     \
        for (int i = 0; i < 4; i++) {                                         \
            uint32_t d_ = cdst + (uint32_t)(i * 32 * ROWB);                   \
            size_t   o_ = (size_t)(i * 32) * DDIM + (cc) * CHUNK;             \
            cpasync16(bb_ + d_, sA0 + o_);                                    \
            cpasync16(bb_ + TILEB + d_, sB0 + o_);                            \
        }                                                                     \
        asm volatile("cp.async.commit_group;" ::: "memory");                  \
    } while (0)

    STAGE(0); STAGE(1);

#pragma unroll
    for (int c = 0; c < NCHUNK; c++) {
        if (c < NCHUNK - 1) asm volatile("cp.async.wait_group 1;" ::: "memory");
        else                asm volatile("cp.async.wait_group 0;" ::: "memory");
        __syncthreads();

        const uint32_t sb = sbase + (uint32_t)((c & 1) * BUFB);
#pragma unroll
        for (int ks = 0; ks < CHUNK / 16; ks++) {
            const uint32_t kx = (uint32_t)(ks * 32);
            uint32_t ah[2][4];
#pragma unroll
            for (int m = 0; m < 2; m++) ldsm4(sb + (aoff[m] ^ kx), ah[m]);
#pragma unroll
            for (int h = 0; h < 2; h++) {
                uint32_t bh[2][4];
#pragma unroll
                for (int s = 0; s < 2; s++)
                    ldsm4(sb + (boff[h][s] ^ kx), bh[s]);
#pragma unroll
                for (int m = 0; m < 2; m++)
#pragma unroll
                    for (int s = 0; s < 2; s++)
#pragma unroll
                        for (int sub = 0; sub < 2; sub++)
                            mma16816(acc[m][h * 4 + s * 2 + sub], ah[m],
                                     bh[s][sub], bh[s][sub + 2]);
            }
        }
        __syncthreads();                 // this stage's readers done
        if (c + 2 < NCHUNK) STAGE(c + 2);  // refill the slot just freed
    }
#undef STAGE

    // ---- epilogue: 5-kernel sum per pair ----
    const float negc = g_negc;
    const int g  = lane >> 2;
    const int c2 = (lane & 3) * 2;
    float fsum = 0.f;
#pragma unroll
    for (int m = 0; m < 2; m++) {
        const int r0 = wr * 32 + m * 16 + g;
        const float s0 = sqA[r0], s1 = sqA[r0 + 8];
#pragma unroll
        for (int nb = 0; nb < 8; nb++) {
            const int cc = wc * 64 + nb * 8 + c2;
            const float t0 = sqB[cc], t1 = sqB[cc + 1];
#pragma unroll
            for (int q = 0; q < 4; q++) {
                const float sr = (q >= 2) ? s1 : s0;
                const float sc = (q & 1) ? t1 : t0;
                float L2 = fmaxf(sr + sc - 2.f * acc[m][nb][q], 0.f);
                float v;
                asm("ex2.approx.ftz.f32 %0, %1;" : "=f"(v) : "f"(L2 * negc));
                float v2 = v * v, v4 = v2 * v2, v8 = v4 * v4, v16 = v8 * v8;
                fsum += v + v2 + v4 + v8 + v16;
            }
        }
    }
    double sgnw = ((bi < 32) == (bj < 32)) ? 1.0 : -1.0;
    if (bj != bi) sgnw *= 2.0;
    double d = (double)fsum * sgnw;
#pragma unroll
    for (int off = 16; off; off >>= 1)
        d += __shfl_down_sync(0xffffffffu, d, off);
    if (lane == 0) wred[w] = d;
    __syncthreads();
    if (t == 0) {
        double s = 0.0;
#pragma unroll
        for (int i = 0; i < 8; i++) s += wred[i];
        g_partial[u] = s;
        __threadfence();
        last_sh = (atomicAdd(&g_done_main, 1u) == NWORK - 1);
    }
    __syncthreads();

    if (!last_sh) return;
    // ---- last-arriving CTA: final reduction ----
    __threadfence();
    double s = 0.0;
    for (int i = t; i < NWORK; i += 256) s += g_partial[i];
    red[t] = s;
    __syncthreads();
    for (int off = 128; off; off >>= 1) {
        if (t < off) red[t] += red[t + off];
        __syncthreads();
    }
    if (t == 0) {
        out[0] = (float)(red[0] / ((double)NX * (double)NX));
        g_done_main = 0;                          // reset for next replay
    }
}

// ---------------------------------------------------------------------------
#define SMEM_DYN (2 * BUFB)   // 65536 B -> 2 CTAs/SM

extern "C" void kernel_launch(void* const* d_in, const int* in_sizes, int n_in,
                              void* d_out, int out_size) {
    const float* x = (const float*)d_in[0];
    const float* y = (const float*)d_in[1];
    (void)in_sizes; (void)n_in; (void)out_size;

    k_prep<<<PBLK, 256>>>(x, y);
    cudaFuncSetAttribute(k_main, cudaFuncAttributeMaxDynamicSharedMemorySize, SMEM_DYN);
    k_main<<<NWORK, 256, SMEM_DYN>>>((float*)d_out);
}